// round 1
// baseline (speedup 1.0000x reference)
#include <cuda_runtime.h>
#include <math.h>

// Problem constants (B=8, V=T=1024, H=1024, L=V+T=2048)
#define BB 8
#define SS 1024
#define HH 1024
#define LL 2048
#define MID_M 341   // t2v active mid rows: 341..681
#define MID_N 512   // keys 256..767

// -------------------- scratch (device globals; no runtime alloc) ------------
__device__ __align__(128) float g_q_text[BB*SS*HH];
__device__ __align__(128) float g_k_vis [BB*SS*HH];
__device__ __align__(128) float g_v_vis [BB*SS*HH];
__device__ __align__(128) float g_q_vis [BB*SS*HH];
__device__ __align__(128) float g_k_text[BB*SS*HH];
__device__ __align__(128) float g_v_text[BB*SS*HH];
__device__ __align__(128) float g_att   [BB*LL*HH];   // attended concat [b, l, h]
__device__ __align__(128) float g_scores[BB*MID_M*MID_N];
__device__ __align__(128) float g_c1    [BB*LL*HH];   // conv1+gelu out [b, l, c]

// -------------------- generic fp32 SGEMM: C = A*B(^T) (+bias) (+resid) ------
// A [M,K] row-major (lda). TRANSB: B [N,K] row-major (ldb) -> C=A*B^T.
// !TRANSB: B [K,N] row-major (ldb) -> C=A*B. N must be a multiple of 128,
// K a multiple of 16 (true for all call sites). M guarded.
template<bool TRANSB, bool BIAS, bool RESID>
__global__ __launch_bounds__(256)
void sgemm_k(const float* __restrict__ A, int lda, long long sA,
             const float* __restrict__ Bm, int ldb, long long sB,
             float* __restrict__ C, int ldc, long long sC,
             const float* __restrict__ bias,
             const float* __restrict__ Rm, int ldr, long long sR,
             int M, int N, int K)
{
    constexpr int Bb = 128, Bn = 128, Bk = 16;
    __shared__ float As[2][Bk][Bb];
    __shared__ float Bs[2][Bk][Bn];

    A  += (long long)blockIdx.z * sA;
    Bm += (long long)blockIdx.z * sB;
    C  += (long long)blockIdx.z * sC;
    if (RESID) Rm += (long long)blockIdx.z * sR;

    const int tid = threadIdx.x;
    const int bx = blockIdx.x, by = blockIdx.y;
    const int ar = tid >> 2;           // 0..63
    const int ac = (tid & 3) << 2;     // 0,4,8,12
    const int br = tid >> 5;           // 0..7
    const int bc = (tid & 31) << 2;    // 0..124

    const int warp = tid >> 5, lane = tid & 31;
    const int mb = (warp & 3) * 32 + (lane >> 3) * 8;
    const int nb = (warp >> 2) * 64 + (lane & 7) * 8;

    float4 aR[2], bR[2];
    float acc[8][8];
    #pragma unroll
    for (int i = 0; i < 8; i++)
        #pragma unroll
        for (int j = 0; j < 8; j++) acc[i][j] = 0.f;

    const int nk = K / Bk;

    // ---- prologue: load tile 0 ----
    {
        const int k0 = 0;
        #pragma unroll
        for (int p = 0; p < 2; p++) {
            int m = by * Bb + ar + p * 64;
            aR[p] = (m < M) ? *(const float4*)(A + (long long)m * lda + k0 + ac)
                            : make_float4(0.f, 0.f, 0.f, 0.f);
        }
        if (TRANSB) {
            #pragma unroll
            for (int p = 0; p < 2; p++) {
                int n = bx * Bn + ar + p * 64;
                bR[p] = *(const float4*)(Bm + (long long)n * ldb + k0 + ac);
            }
        } else {
            #pragma unroll
            for (int p = 0; p < 2; p++) {
                int kk = br + p * 8;
                bR[p] = *(const float4*)(Bm + (long long)(k0 + kk) * ldb + bx * Bn + bc);
            }
        }
    }
    int buf = 0;
    #pragma unroll
    for (int p = 0; p < 2; p++) {
        As[buf][ac + 0][ar + p * 64] = aR[p].x;
        As[buf][ac + 1][ar + p * 64] = aR[p].y;
        As[buf][ac + 2][ar + p * 64] = aR[p].z;
        As[buf][ac + 3][ar + p * 64] = aR[p].w;
    }
    if (TRANSB) {
        #pragma unroll
        for (int p = 0; p < 2; p++) {
            Bs[buf][ac + 0][ar + p * 64] = bR[p].x;
            Bs[buf][ac + 1][ar + p * 64] = bR[p].y;
            Bs[buf][ac + 2][ar + p * 64] = bR[p].z;
            Bs[buf][ac + 3][ar + p * 64] = bR[p].w;
        }
    } else {
        #pragma unroll
        for (int p = 0; p < 2; p++)
            *(float4*)&Bs[buf][br + p * 8][bc] = bR[p];
    }
    __syncthreads();

    for (int kt = 0; kt < nk; kt++) {
        const bool more = (kt + 1 < nk);
        if (more) {
            const int k0 = (kt + 1) * Bk;
            #pragma unroll
            for (int p = 0; p < 2; p++) {
                int m = by * Bb + ar + p * 64;
                aR[p] = (m < M) ? *(const float4*)(A + (long long)m * lda + k0 + ac)
                                : make_float4(0.f, 0.f, 0.f, 0.f);
            }
            if (TRANSB) {
                #pragma unroll
                for (int p = 0; p < 2; p++) {
                    int n = bx * Bn + ar + p * 64;
                    bR[p] = *(const float4*)(Bm + (long long)n * ldb + k0 + ac);
                }
            } else {
                #pragma unroll
                for (int p = 0; p < 2; p++) {
                    int kk = br + p * 8;
                    bR[p] = *(const float4*)(Bm + (long long)(k0 + kk) * ldb + bx * Bn + bc);
                }
            }
        }
        #pragma unroll
        for (int k = 0; k < Bk; k++) {
            float a[8], bv2[8];
            *(float4*)&a[0]   = *(const float4*)&As[buf][k][mb];
            *(float4*)&a[4]   = *(const float4*)&As[buf][k][mb + 4];
            *(float4*)&bv2[0] = *(const float4*)&Bs[buf][k][nb];
            *(float4*)&bv2[4] = *(const float4*)&Bs[buf][k][nb + 4];
            #pragma unroll
            for (int i = 0; i < 8; i++)
                #pragma unroll
                for (int j = 0; j < 8; j++)
                    acc[i][j] += a[i] * bv2[j];
        }
        if (more) {
            buf ^= 1;
            #pragma unroll
            for (int p = 0; p < 2; p++) {
                As[buf][ac + 0][ar + p * 64] = aR[p].x;
                As[buf][ac + 1][ar + p * 64] = aR[p].y;
                As[buf][ac + 2][ar + p * 64] = aR[p].z;
                As[buf][ac + 3][ar + p * 64] = aR[p].w;
            }
            if (TRANSB) {
                #pragma unroll
                for (int p = 0; p < 2; p++) {
                    Bs[buf][ac + 0][ar + p * 64] = bR[p].x;
                    Bs[buf][ac + 1][ar + p * 64] = bR[p].y;
                    Bs[buf][ac + 2][ar + p * 64] = bR[p].z;
                    Bs[buf][ac + 3][ar + p * 64] = bR[p].w;
                }
            } else {
                #pragma unroll
                for (int p = 0; p < 2; p++)
                    *(float4*)&Bs[buf][br + p * 8][bc] = bR[p];
            }
            __syncthreads();
        }
    }

    // ---- epilogue ----
    float bvv[8];
    if (BIAS) {
        #pragma unroll
        for (int j = 0; j < 8; j++) bvv[j] = bias[bx * Bn + nb + j];
    }
    #pragma unroll
    for (int i = 0; i < 8; i++) {
        int m = by * Bb + mb + i;
        if (m < M) {
            float* Cp = C + (long long)m * ldc + bx * Bn + nb;
            const float* Rp = RESID ? (Rm + (long long)m * ldr + bx * Bn + nb) : (const float*)0;
            #pragma unroll
            for (int j = 0; j < 8; j += 4) {
                float4 v;
                v.x = acc[i][j + 0]; v.y = acc[i][j + 1];
                v.z = acc[i][j + 2]; v.w = acc[i][j + 3];
                if (BIAS) { v.x += bvv[j]; v.y += bvv[j + 1]; v.z += bvv[j + 2]; v.w += bvv[j + 3]; }
                if (RESID) {
                    float4 rv = *(const float4*)(Rp + j);
                    v.x += rv.x; v.y += rv.y; v.z += rv.z; v.w += rv.w;
                }
                *(float4*)(Cp + j) = v;
            }
        }
    }
}

// -------------------- copy text features into concat buffer ----------------
__global__ void copy_text(const float4* __restrict__ src, float4* __restrict__ dst)
{
    int idx = blockIdx.x * 256 + threadIdx.x;        // total 8*1024*1024/4 = 2M
    int b = idx >> 18;                               // / 262144
    int r = idx & 262143;
    dst[(long long)b * 524288 + 262144 + r] = src[idx];
}

// -------------------- v2t attention (<=13 keys/row) + residual --------------
__global__ __launch_bounds__(128) void v2t_attn(
    const float* __restrict__ qvis, const float* __restrict__ ktext,
    const float* __restrict__ vtext, const float* __restrict__ visf,
    float* __restrict__ att)
{
    const int i = blockIdx.x, b = blockIdx.y;
    const int tid = threadIdx.x, lane = tid & 31, warp = tid >> 5;
    const int s0 = (i < 1016) ? i : 1016;
    const int nk = (i < 5) ? (i + 8) : 13;   // union of {0..4} and window

    const float* q = qvis + ((long long)b * SS + i) * HH;
    float qr[8];
    #pragma unroll
    for (int r = 0; r < 8; r++) qr[r] = q[r * 128 + tid];

    const float* kb = ktext + (long long)b * SS * HH;
    float p[13];
    #pragma unroll
    for (int j = 0; j < 13; j++) {
        float s = 0.f;
        if (j < nk) {
            int kj = (i < 5) ? j : ((j < 5) ? j : (s0 + j - 5));
            const float* kp = kb + (long long)kj * HH + tid;
            #pragma unroll
            for (int r = 0; r < 8; r++) s += qr[r] * kp[r * 128];
        }
        p[j] = s;
    }
    #pragma unroll
    for (int j = 0; j < 13; j++) {
        #pragma unroll
        for (int off = 16; off; off >>= 1) p[j] += __shfl_xor_sync(0xffffffffu, p[j], off);
    }
    __shared__ float red[4][13];
    if (lane == 0) {
        #pragma unroll
        for (int j = 0; j < 13; j++) red[warp][j] = p[j];
    }
    __syncthreads();

    float sc[13];
    float mx = -3.4e38f;
    #pragma unroll
    for (int j = 0; j < 13; j++) {
        sc[j] = red[0][j] + red[1][j] + red[2][j] + red[3][j];
        if (j < nk) mx = fmaxf(mx, sc[j]);
    }
    float sum = 0.f;
    #pragma unroll
    for (int j = 0; j < 13; j++) {
        float e = (j < nk) ? expf(sc[j] - mx) : 0.f;
        sc[j] = e; sum += e;
    }
    const float inv = 1.f / sum;

    const float* vf = visf + ((long long)b * SS + i) * HH;
    const float* vb = vtext + (long long)b * SS * HH;
    float* op = att + ((long long)b * LL + i) * HH;
    #pragma unroll
    for (int r = 0; r < 8; r++) {
        int h = r * 128 + tid;
        float a2 = vf[h];
        #pragma unroll
        for (int j = 0; j < 13; j++) {
            if (j < nk) {
                int kj = (i < 5) ? j : ((j < 5) ? j : (s0 + j - 5));
                a2 += sc[j] * inv * vb[(long long)kj * HH + h];
            }
        }
        op[h] = a2;
    }
}

// -------------------- t2v rows 0..4 (full softmax over 1024 keys) -----------
__global__ __launch_bounds__(256) void t2v_full_rows(
    const float* __restrict__ qtext, const float* __restrict__ kvis,
    const float* __restrict__ vvis, float* __restrict__ att)
{
    const int r = blockIdx.x, b = blockIdx.y;
    const int tid = threadIdx.x, lane = tid & 31, warp = tid >> 5;
    __shared__ float qs[1024];
    __shared__ float sc[1024];
    __shared__ float red[8];

    const float* q = qtext + ((long long)b * SS + r) * HH;
    for (int h = tid; h < 1024; h += 256) qs[h] = q[h];
    __syncthreads();

    const float* kb = kvis + (long long)b * SS * HH;
    for (int t = warp * 128; t < warp * 128 + 128; t++) {
        const float* kp = kb + (long long)t * HH;
        float p = 0.f;
        #pragma unroll
        for (int c = 0; c < 32; c++) p += qs[c * 32 + lane] * kp[c * 32 + lane];
        #pragma unroll
        for (int off = 16; off; off >>= 1) p += __shfl_xor_sync(0xffffffffu, p, off);
        if (lane == 0) sc[t] = p;
    }
    __syncthreads();

    float m = -3.4e38f;
    for (int t = tid; t < 1024; t += 256) m = fmaxf(m, sc[t]);
    #pragma unroll
    for (int off = 16; off; off >>= 1) m = fmaxf(m, __shfl_xor_sync(0xffffffffu, m, off));
    if (lane == 0) red[warp] = m;
    __syncthreads();
    float mx = red[0];
    #pragma unroll
    for (int k = 1; k < 8; k++) mx = fmaxf(mx, red[k]);

    float s = 0.f;
    for (int t = tid; t < 1024; t += 256) { float e = expf(sc[t] - mx); sc[t] = e; s += e; }
    #pragma unroll
    for (int off = 16; off; off >>= 1) s += __shfl_xor_sync(0xffffffffu, s, off);
    __syncthreads();            // protect red reuse; also publishes sc[]
    if (lane == 0) red[warp] = s;
    __syncthreads();
    float tot = 0.f;
    #pragma unroll
    for (int k = 0; k < 8; k++) tot += red[k];
    const float inv = 1.f / tot;

    const float* vb = vvis + (long long)b * SS * HH;
    float* op = att + ((long long)b * LL + 1024 + r) * HH;
    float accv[4] = {0.f, 0.f, 0.f, 0.f};
    for (int t = 0; t < 1024; t++) {
        float pw = sc[t];
        const float* vr = vb + (long long)t * HH + tid;
        accv[0] += pw * vr[0];
        accv[1] += pw * vr[256];
        accv[2] += pw * vr[512];
        accv[3] += pw * vr[768];
    }
    #pragma unroll
    for (int k = 0; k < 4; k++) op[tid + k * 256] += accv[k] * inv;
}

// -------------------- softmax over 512-col rows (t2v mid block) -------------
__global__ __launch_bounds__(256) void softmax512(float* __restrict__ S)
{
    float* row = S + (long long)blockIdx.x * 512;
    const int tid = threadIdx.x, lane = tid & 31, warp = tid >> 5;
    __shared__ float red[8];
    float a = row[tid], b2 = row[tid + 256];
    float m = fmaxf(a, b2);
    #pragma unroll
    for (int off = 16; off; off >>= 1) m = fmaxf(m, __shfl_xor_sync(0xffffffffu, m, off));
    if (lane == 0) red[warp] = m;
    __syncthreads();
    float mx = red[0];
    #pragma unroll
    for (int k = 1; k < 8; k++) mx = fmaxf(mx, red[k]);
    float e0 = expf(a - mx), e1 = expf(b2 - mx);
    float s = e0 + e1;
    #pragma unroll
    for (int off = 16; off; off >>= 1) s += __shfl_xor_sync(0xffffffffu, s, off);
    __syncthreads();
    if (lane == 0) red[warp] = s;
    __syncthreads();
    float tot = 0.f;
    #pragma unroll
    for (int k = 0; k < 8; k++) tot += red[k];
    float inv = 1.f / tot;
    row[tid] = e0 * inv;
    row[tid + 256] = e1 * inv;
}

// -------------------- grouped conv1 (k=3, groups=8) + exact GELU ------------
__global__ __launch_bounds__(128) void conv1_gelu(
    const float* __restrict__ att, const float* __restrict__ W,
    const float* __restrict__ bias, float* __restrict__ out)
{
    __shared__ float s[34][128];      // input tile: l0-1 .. l0+32, 128 channels of group
    __shared__ float Ws[128][49];     // 16 input channels * 3 taps = 48 weights / out-ch
    const int b = blockIdx.z, g = blockIdx.y;
    const int l0 = blockIdx.x * 32;
    const int tid = threadIdx.x;

    const float* base = att + (long long)b * LL * HH + g * 128;
    #pragma unroll
    for (int j = 0; j < 34; j++) {
        int l = l0 - 1 + j;
        s[j][tid] = (l >= 0 && l < LL) ? base[(long long)l * HH + tid] : 0.f;
    }
    const int o = g * 128 + tid;
    float acc[32];
    #pragma unroll
    for (int l = 0; l < 32; l++) acc[l] = 0.f;

    for (int ic = 0; ic < 8; ic++) {
        __syncthreads();                      // covers s[] on first pass, Ws reuse after
        for (int t = tid; t < 128 * 48; t += 128) {
            int oo = t / 48, j = t % 48;
            Ws[oo][j] = W[((long long)(g * 128 + oo)) * 384 + ic * 48 + j];
        }
        __syncthreads();
        #pragma unroll
        for (int ii = 0; ii < 16; ii++) {
            int i = ic * 16 + ii;
            float w0 = Ws[tid][ii * 3 + 0];
            float w1 = Ws[tid][ii * 3 + 1];
            float w2 = Ws[tid][ii * 3 + 2];
            #pragma unroll
            for (int l = 0; l < 32; l++)
                acc[l] += w0 * s[l][i] + w1 * s[l + 1][i] + w2 * s[l + 2][i];
        }
    }
    const float bo = bias[o];
    float* op = out + ((long long)b * LL + l0) * HH + o;
    #pragma unroll
    for (int l = 0; l < 32; l++) {
        float x = acc[l] + bo;
        float y = 0.5f * x * (1.0f + erff(x * 0.70710678118654752f));   // exact GELU
        op[(long long)l * HH] = y;
    }
}

// -------------------- launcher ----------------------------------------------
extern "C" void kernel_launch(void* const* d_in, const int* in_sizes, int n_in,
                              void* d_out, int out_size)
{
    (void)in_sizes; (void)n_in; (void)out_size;
    const float* vis = (const float*)d_in[0];
    const float* txt = (const float*)d_in[1];
    const float* Wq  = (const float*)d_in[2];  const float* bq  = (const float*)d_in[3];
    const float* Wk  = (const float*)d_in[4];  const float* bk  = (const float*)d_in[5];
    const float* Wv  = (const float*)d_in[6];  const float* bv  = (const float*)d_in[7];
    const float* Wc1 = (const float*)d_in[8];  const float* bc1 = (const float*)d_in[9];
    const float* Wc2 = (const float*)d_in[10]; const float* bc2 = (const float*)d_in[11];
    float* out = (float*)d_out;

    float *qt, *kv, *vv, *qv, *kt, *vt, *attb, *scb, *c1b;
    cudaGetSymbolAddress((void**)&qt,  g_q_text);
    cudaGetSymbolAddress((void**)&kv,  g_k_vis);
    cudaGetSymbolAddress((void**)&vv,  g_v_vis);
    cudaGetSymbolAddress((void**)&qv,  g_q_vis);
    cudaGetSymbolAddress((void**)&kt,  g_k_text);
    cudaGetSymbolAddress((void**)&vt,  g_v_text);
    cudaGetSymbolAddress((void**)&attb, g_att);
    cudaGetSymbolAddress((void**)&scb, g_scores);
    cudaGetSymbolAddress((void**)&c1b, g_c1);

    const long long SH = (long long)SS * HH;       // 1048576
    const long long LH = (long long)LL * HH;       // 2097152
    const long long SCs = (long long)MID_M * MID_N; // 174592

    // 1) projections: [8192,1024] @ W^T + bias
    dim3 gP(HH / 128, (BB * SS) / 128, 1);
    sgemm_k<true, true, false><<<gP, 256>>>(txt, HH, 0, Wq, HH, 0, qt, HH, 0, bq, nullptr, 0, 0, BB*SS, HH, HH);
    sgemm_k<true, true, false><<<gP, 256>>>(vis, HH, 0, Wk, HH, 0, kv, HH, 0, bk, nullptr, 0, 0, BB*SS, HH, HH);
    sgemm_k<true, true, false><<<gP, 256>>>(vis, HH, 0, Wv, HH, 0, vv, HH, 0, bv, nullptr, 0, 0, BB*SS, HH, HH);
    sgemm_k<true, true, false><<<gP, 256>>>(vis, HH, 0, Wq, HH, 0, qv, HH, 0, bq, nullptr, 0, 0, BB*SS, HH, HH);
    sgemm_k<true, true, false><<<gP, 256>>>(txt, HH, 0, Wk, HH, 0, kt, HH, 0, bk, nullptr, 0, 0, BB*SS, HH, HH);
    sgemm_k<true, true, false><<<gP, 256>>>(txt, HH, 0, Wv, HH, 0, vt, HH, 0, bv, nullptr, 0, 0, BB*SS, HH, HH);

    // 2) init text half of concat buffer with residual text features
    copy_text<<<8192, 256>>>((const float4*)txt, (float4*)attb);

    // 3) v2t sparse attention (<=13 keys) + visual residual -> att rows [0,1024)
    v2t_attn<<<dim3(SS, BB), 128>>>(qv, kt, vt, vis, attb);

    // 4) t2v rows 0..4: full softmax over all visual keys, add into text rows
    t2v_full_rows<<<dim3(5, BB), 256>>>(qt, kv, vv, attb);

    // 5) t2v mid block: scores [341,512] = q_text[341:682] @ k_vis[256:768]^T
    sgemm_k<true, false, false><<<dim3(MID_N / 128, 3, BB), 256>>>(
        qt + 341 * HH, HH, SH, kv + 256 * HH, HH, SH,
        scb, MID_N, SCs, nullptr, nullptr, 0, 0, MID_M, MID_N, HH);

    // 6) row softmax over 512 cols
    softmax512<<<BB * MID_M, 256>>>(scb);

    // 7) AV: att_text[341:682] = text_resid + probs @ v_vis[256:768]
    sgemm_k<false, false, true><<<dim3(HH / 128, 3, BB), 256>>>(
        scb, MID_N, SCs, vv + 256 * HH, HH, SH,
        attb + (long long)(1024 + 341) * HH, HH, LH,
        nullptr, txt + 341 * HH, HH, SH, MID_M, HH, MID_N);

    // 8) grouped conv1 (k=3, groups=8) + exact GELU
    conv1_gelu<<<dim3(LL / 32, 8, BB), 128>>>(attb, Wc1, bc1, c1b);

    // 9) pointwise conv2 as GEMM -> output [B, V+T, H]
    sgemm_k<true, true, false><<<dim3(HH / 128, (BB * LL) / 128, 1), 256>>>(
        c1b, HH, 0, Wc2, HH, 0, out, HH, 0, bc2, nullptr, 0, 0, BB * LL, HH, HH);
}